// round 12
// baseline (speedup 1.0000x reference)
#include <cuda_runtime.h>
#include <cuda_fp16.h>
#include <cstdint>

// ===================== Problem constants =====================
#define B_DIM 8192
#define P_DIM 24
#define Q_DIM 12
#define E_DIM 256
#define V_DIM 1000
#define LN_EPS 1e-5f

#define GEMM_CTAS 768          // 24 p * 32 mslots; CTA = 4 tiles of 64 rows (512 thr)
#define CAT_CTAS 192
#define TOK_PER_CAT_CTA 512    // 98304 / 192

// fp16 transposed W2: [p][f][e], intermediate
__device__ __half g_W2Th[P_DIM * E_DIM * E_DIM];
// fragment-packed W2: [p][ks(16)][ntp(16)][lane(32)] uint4  (3.1 MB)
__device__ uint4 g_W2Tf[P_DIM * 16 * 16 * 32];

// ===================== Kernel 0: transpose + halve W2 =====================
__global__ void w2t_kernel(const float* __restrict__ W2) {
    __shared__ float tile[32][33];
    int p  = blockIdx.z;
    int e0 = blockIdx.y * 32;
    int f0 = blockIdx.x * 32;
    int tx = threadIdx.x, ty = threadIdx.y;
    #pragma unroll
    for (int i = ty; i < 32; i += 8)
        tile[i][tx] = W2[((size_t)p * 256 + e0 + i) * 256 + f0 + tx];
    __syncthreads();
    #pragma unroll
    for (int i = ty; i < 32; i += 8) {
        float v = tile[tx][i];
        g_W2Th[((size_t)p * 256 + f0 + i) * 256 + e0 + tx] = __float2half_rn(v);
    }
}

// ===================== Kernel 1: pack W2 fragments =====================
__global__ __launch_bounds__(256)
void pack_kernel() {
    const int p    = blockIdx.x;
    const int lane = threadIdx.x & 31;
    const int warp = threadIdx.x >> 5;   // 0..7
    const uint32_t* w2pu = (const uint32_t*)(g_W2Th + (size_t)p * 65536);
    uint4* dstb = g_W2Tf + (size_t)p * 8192;
    #pragma unroll
    for (int kk = 0; kk < 2; kk++) {
        const int ks = warp * 2 + kk;
        const int ne_base = lane >> 2;
        const int kh0 = ks * 8 + (lane & 3);
        const int kh1 = kh0 + 4;
        #pragma unroll
        for (int ntp = 0; ntp < 16; ntp++) {
            const int n_e = 2 * ntp * 8 + ne_base;
            const int n_o = n_e + 8;
            uint4 v;
            v.x = w2pu[n_e * 128 + kh0];
            v.y = w2pu[n_e * 128 + kh1];
            v.z = w2pu[n_o * 128 + kh0];
            v.w = w2pu[n_o * 128 + kh1];
            dstb[(ks * 16 + ntp) * 32 + lane] = v;
        }
    }
}

// ---- fast gelu (validated: rel_err identical to erff version) ----
__device__ __forceinline__ float fast_gelu(float t) {
    const float z  = fabsf(t) * 0.70710678118654752f;
    const float k  = __fdividef(1.0f, fmaf(0.3275911f, z, 1.0f));
    float pk = fmaf(1.061405429f, k, -1.453152027f);
    pk = fmaf(pk, k, 1.421413741f);
    pk = fmaf(pk, k, -0.284496736f);
    pk = fmaf(pk, k, 0.254829592f);
    pk = pk * k;
    const float ez   = __expf(-z * z);
    const float erfv = fmaf(-pk, ez, 1.0f);
    const float e    = (t >= 0.f) ? erfv : -erfv;
    return 0.5f * t * (1.0f + e);
}

// ===================== Fused kernel: 512 threads, tile-pipelined =====================
// SMEM byte offsets
#define SM_X    0        // 2 x 64 f = 512 B
#define SM_W1   1024     // 256 f
#define SM_B1   2048
#define SM_B2   3072
#define SM_G    4096
#define SM_BE   5120
#define SM_STAT 6144     // 64 rows x 16 f = 4096 B (ends 10240)
#define SM_A    16384    // 2 x 32768 B : A frags [ks(16)][mti(4)][lane(32)] uint4
#define SM_B    81920    // 131072 B : B frags [ks(16)][ntp(16)][lane(32)] uint4
#define GEMM_SMEM (81920 + 131072)   // 212992

__device__ __forceinline__ void mma16816(float* c, const uint32_t* a, const uint32_t* b) {
    asm volatile(
        "mma.sync.aligned.m16n8k16.row.col.f32.f16.f16.f32 "
        "{%0,%1,%2,%3}, {%4,%5,%6,%7}, {%8,%9}, {%0,%1,%2,%3};\n"
        : "+f"(c[0]), "+f"(c[1]), "+f"(c[2]), "+f"(c[3])
        : "r"(a[0]), "r"(a[1]), "r"(a[2]), "r"(a[3]), "r"(b[0]), "r"(b[1]));
}

// gelu prologue for one tile: warp w owns ks = w (16 warps x 4 mti slots)
__device__ __forceinline__ void prologueA(uint4* abuf, const float* xs,
                                          const float* w1s, const float* b1s,
                                          int warp, int lane) {
    const int ks = warp;
    const int kbase = ks * 16 + (lane & 3) * 2;
    #pragma unroll
    for (int mti = 0; mti < 4; mti++) {
        const float xm0 = xs[mti * 16 + (lane >> 2)];
        const float xm1 = xs[mti * 16 + (lane >> 2) + 8];
        uint32_t r[4];
        #pragma unroll
        for (int reg = 0; reg < 4; reg++) {
            const float xm = (reg & 1) ? xm1 : xm0;
            const int k = kbase + (reg & 2) * 4;
            float h0 = fast_gelu(fmaf(xm, w1s[k],     b1s[k]));
            float h1 = fast_gelu(fmaf(xm, w1s[k + 1], b1s[k + 1]));
            __half2 hv = __floats2half2_rn(h0, h1);
            r[reg] = *reinterpret_cast<uint32_t*>(&hv);
        }
        abuf[(ks * 4 + mti) * 32 + lane] = make_uint4(r[0], r[1], r[2], r[3]);
    }
}

__global__ __launch_bounds__(512, 1)
void fused_kernel(const float* __restrict__ x_num,
                  const int*   __restrict__ x_cat,
                  const float* __restrict__ W1,
                  const float* __restrict__ b1,
                  const float* __restrict__ b2,
                  const float* __restrict__ emb,
                  const float* __restrict__ gamma,
                  const float* __restrict__ beta,
                  float* __restrict__ out) {
    const int tid  = threadIdx.x;
    const int lane = tid & 31;
    const int warp = tid >> 5;       // 0..15

    // ================= CAT PATH (2 independent tokens per warp-iter) =================
    if (blockIdx.x >= GEMM_CTAS) {
        const int blk2 = blockIdx.x - GEMM_CTAS;
        const float4* g4  = (const float4*)gamma;
        const float4* be4 = (const float4*)beta;
        float4 g0 = g4[lane], g1 = g4[lane + 32];
        float4 e0 = be4[lane], e1 = be4[lane + 32];

        #pragma unroll 1
        for (int it = 0; it < TOK_PER_CAT_CTA / 32; it++) {
            const int tokA = blk2 * TOK_PER_CAT_CTA + it * 32 + warp * 2;
            const int tokB = tokA + 1;
            const int bA = tokA / Q_DIM, qA = tokA % Q_DIM;
            const int bB = tokB / Q_DIM, qB = tokB % Q_DIM;
            const int idxA = x_cat[(size_t)bA * Q_DIM + qA];
            const int idxB = x_cat[(size_t)bB * Q_DIM + qB];
            const float4* srcA = (const float4*)(emb + ((size_t)qA * V_DIM + idxA) * E_DIM);
            const float4* srcB = (const float4*)(emb + ((size_t)qB * V_DIM + idxB) * E_DIM);
            float4 a0 = srcA[lane], a1 = srcA[lane + 32];
            float4 c0 = srcB[lane], c1 = srcB[lane + 32];

            float sa = a0.x + a0.y + a0.z + a0.w + a1.x + a1.y + a1.z + a1.w;
            float qa = a0.x * a0.x + a0.y * a0.y + a0.z * a0.z + a0.w * a0.w
                     + a1.x * a1.x + a1.y * a1.y + a1.z * a1.z + a1.w * a1.w;
            float sb = c0.x + c0.y + c0.z + c0.w + c1.x + c1.y + c1.z + c1.w;
            float qb = c0.x * c0.x + c0.y * c0.y + c0.z * c0.z + c0.w * c0.w
                     + c1.x * c1.x + c1.y * c1.y + c1.z * c1.z + c1.w * c1.w;
            #pragma unroll
            for (int off = 16; off > 0; off >>= 1) {
                sa += __shfl_xor_sync(0xFFFFFFFFu, sa, off);
                qa += __shfl_xor_sync(0xFFFFFFFFu, qa, off);
                sb += __shfl_xor_sync(0xFFFFFFFFu, sb, off);
                qb += __shfl_xor_sync(0xFFFFFFFFu, qb, off);
            }
            const float muA = sa * (1.0f / 256.0f);
            const float rsA = rsqrtf(qa * (1.0f / 256.0f) - muA * muA + LN_EPS);
            const float muB = sb * (1.0f / 256.0f);
            const float rsB = rsqrtf(qb * (1.0f / 256.0f) - muB * muB + LN_EPS);

            float4 r0, r1;
            r0.x = (a0.x - muA) * rsA * g0.x + e0.x;
            r0.y = (a0.y - muA) * rsA * g0.y + e0.y;
            r0.z = (a0.z - muA) * rsA * g0.z + e0.z;
            r0.w = (a0.w - muA) * rsA * g0.w + e0.w;
            r1.x = (a1.x - muA) * rsA * g1.x + e1.x;
            r1.y = (a1.y - muA) * rsA * g1.y + e1.y;
            r1.z = (a1.z - muA) * rsA * g1.z + e1.z;
            r1.w = (a1.w - muA) * rsA * g1.w + e1.w;
            float4* dstA = (float4*)(out + ((size_t)bA * 36 + 24 + qA) * E_DIM);
            dstA[lane] = r0;
            dstA[lane + 32] = r1;

            r0.x = (c0.x - muB) * rsB * g0.x + e0.x;
            r0.y = (c0.y - muB) * rsB * g0.y + e0.y;
            r0.z = (c0.z - muB) * rsB * g0.z + e0.z;
            r0.w = (c0.w - muB) * rsB * g0.w + e0.w;
            r1.x = (c1.x - muB) * rsB * g1.x + e1.x;
            r1.y = (c1.y - muB) * rsB * g1.y + e1.y;
            r1.z = (c1.z - muB) * rsB * g1.z + e1.z;
            r1.w = (c1.w - muB) * rsB * g1.w + e1.w;
            float4* dstB = (float4*)(out + ((size_t)bB * 36 + 24 + qB) * E_DIM);
            dstB[lane] = r0;
            dstB[lane + 32] = r1;
        }
        return;
    }

    // ================= GEMM PATH =================
    extern __shared__ char smem[];
    const int p     = blockIdx.x >> 5;   // 0..23
    const int mslot = blockIdx.x & 31;   // 0..31

    float* xsb[2] = { (float*)(smem + SM_X), (float*)(smem + SM_X) + 64 };
    float* w1s = (float*)(smem + SM_W1);
    float* b1s = (float*)(smem + SM_B1);
    float* b2s = (float*)(smem + SM_B2);
    float* gs  = (float*)(smem + SM_G);
    float* bes = (float*)(smem + SM_BE);
    float* statb = (float*)(smem + SM_STAT);          // [64][16]
    uint4* abufs[2] = { (uint4*)(smem + SM_A), (uint4*)(smem + SM_A + 32768) };
    uint4* bfrag = (uint4*)(smem + SM_B);

    if (tid < 256) {
        w1s[tid] = W1[p * 256 + tid];
        b1s[tid] = b1[p * 256 + tid];
        b2s[tid] = b2[p * 256 + tid];
        gs[tid]  = gamma[tid];
        bes[tid] = beta[tid];
    }

    // ---- Stage B frags ONCE: warp = ks ----
    {
        const uint4* w2f = g_W2Tf + (size_t)p * 8192 + warp * 512 + lane;
        uint4* dst = bfrag + warp * 512 + lane;
        #pragma unroll
        for (int ntp = 0; ntp < 16; ntp++)
            dst[ntp * 32] = w2f[ntp * 32];
    }

    // ---- Preload xs for tiles 0 and 1 ----
    if (tid < 64)
        xsb[0][tid] = x_num[(size_t)((mslot * 4 + 0) * 64 + tid) * P_DIM + p];
    else if (tid < 128)
        xsb[1][tid - 64] = x_num[(size_t)((mslot * 4 + 1) * 64 + (tid - 64)) * P_DIM + p];
    __syncthreads();

    // ---- Prologue A[0] ----
    prologueA(abufs[0], xsb[0], w1s, b1s, warp, lane);
    __syncthreads();

    const int wm = warp & 1;    // row half (0..1): rows wm*32..wm*32+31
    const int wn = warp >> 1;   // n octet (0..7): cols wn*32..wn*32+31

    float2 b2v[4];
    #pragma unroll
    for (int ntl = 0; ntl < 4; ntl++)
        b2v[ntl] = *(float2*)&b2s[wn * 32 + ntl * 8 + (lane & 3) * 2];

    // ---- Tile loop: 4 tiles of 64 rows ----
    for (int t = 0; t < 4; t++) {
        const int cur = t & 1, nxt = cur ^ 1;
        const int m0 = (mslot * 4 + t) * 64;

        // ===== Phase a: xs prefetch + mainloop(A[cur]) + prologue(A[nxt]) =====
        if (t < 2 && tid < 64)
            xsb[cur][tid] = x_num[(size_t)((mslot * 4 + t + 2) * 64 + tid) * P_DIM + p];

        float acc[2][4][4];
        #pragma unroll
        for (int i = 0; i < 2; i++)
            #pragma unroll
            for (int j = 0; j < 4; j++)
                #pragma unroll
                for (int r = 0; r < 4; r++) acc[i][j][r] = 0.f;

        {
            const uint4* af = abufs[cur];
            #pragma unroll
            for (int ks = 0; ks < 16; ks++) {
                uint32_t a[2][4];
                #pragma unroll
                for (int mr = 0; mr < 2; mr++) {
                    uint4 v = af[(ks * 4 + wm * 2 + mr) * 32 + lane];
                    a[mr][0] = v.x; a[mr][1] = v.y; a[mr][2] = v.z; a[mr][3] = v.w;
                }
                #pragma unroll
                for (int i = 0; i < 2; i++) {
                    uint4 bv4 = bfrag[(ks * 16 + wn * 2 + i) * 32 + lane];
                    uint32_t b0[2] = {bv4.x, bv4.y};
                    uint32_t b1r[2] = {bv4.z, bv4.w};
                    #pragma unroll
                    for (int mr = 0; mr < 2; mr++) {
                        mma16816(acc[mr][i * 2],     a[mr], b0);
                        mma16816(acc[mr][i * 2 + 1], a[mr], b1r);
                    }
                }
            }
        }
        if (t < 3)
            prologueA(abufs[nxt], xsb[nxt], w1s, b1s, warp, lane);
        __syncthreads();    // A[nxt] complete; all reads of A[cur]/xs done

        // ===== Phase b: +b2, row-partial stats -> statb =====
        #pragma unroll
        for (int mr = 0; mr < 2; mr++)
            #pragma unroll
            for (int ntl = 0; ntl < 4; ntl++) {
                acc[mr][ntl][0] += b2v[ntl].x;
                acc[mr][ntl][1] += b2v[ntl].y;
                acc[mr][ntl][2] += b2v[ntl].x;
                acc[mr][ntl][3] += b2v[ntl].y;
            }

        #pragma unroll
        for (int mr = 0; mr < 2; mr++)
            #pragma unroll
            for (int h = 0; h < 2; h++) {
                float s = 0.f, q = 0.f;
                #pragma unroll
                for (int ntl = 0; ntl < 4; ntl++) {
                    float v0 = acc[mr][ntl][h * 2];
                    float v1 = acc[mr][ntl][h * 2 + 1];
                    s += v0 + v1;
                    q += v0 * v0 + v1 * v1;
                }
                s += __shfl_xor_sync(0xFFFFFFFFu, s, 1);
                q += __shfl_xor_sync(0xFFFFFFFFu, q, 1);
                s += __shfl_xor_sync(0xFFFFFFFFu, s, 2);
                q += __shfl_xor_sync(0xFFFFFFFFu, q, 2);
                if ((lane & 3) == 0) {
                    const int row = wm * 32 + mr * 16 + (lane >> 2) + h * 8;
                    *(float2*)&statb[row * 16 + wn * 2] = make_float2(s, q);
                }
            }
        __syncthreads();    // stats visible

        // ===== Phase c: normalize + store =====
        #pragma unroll
        for (int mr = 0; mr < 2; mr++)
            #pragma unroll
            for (int h = 0; h < 2; h++) {
                const int row = wm * 32 + mr * 16 + (lane >> 2) + h * 8;
                float sum = 0.f, sq = 0.f;
                #pragma unroll
                for (int j = 0; j < 4; j++) {
                    float4 v = *(float4*)&statb[row * 16 + j * 4];
                    sum += v.x + v.z;
                    sq  += v.y + v.w;
                }
                const float mu   = sum * (1.0f / 256.0f);
                const float var  = sq * (1.0f / 256.0f) - mu * mu;
                const float rstd = rsqrtf(var + LN_EPS);

                float* orow = out + (((size_t)(m0 + row) * 36 + p) * 256);
                #pragma unroll
                for (int ntl = 0; ntl < 4; ntl++) {
                    const int col = wn * 32 + ntl * 8 + (lane & 3) * 2;
                    const float2 gvv = *(float2*)&gs[col];
                    const float2 bvv = *(float2*)&bes[col];
                    float2 r;
                    r.x = (acc[mr][ntl][h * 2]     - mu) * rstd * gvv.x + bvv.x;
                    r.y = (acc[mr][ntl][h * 2 + 1] - mu) * rstd * gvv.y + bvv.y;
                    *(float2*)&orow[col] = r;
                }
            }
        // no sync needed here: next phase a touches only A/xs/B; statb is
        // rewritten in phase b(t+1), separated from these reads by sync1(t+1).
    }
}

// ===================== Launch =====================
extern "C" void kernel_launch(void* const* d_in, const int* in_sizes, int n_in,
                              void* d_out, int out_size) {
    const float* x_num = (const float*)d_in[0];
    const int*   x_cat = (const int*)d_in[1];
    const float* W1    = (const float*)d_in[2];
    const float* b1    = (const float*)d_in[3];
    const float* W2    = (const float*)d_in[4];
    const float* b2    = (const float*)d_in[5];
    const float* emb   = (const float*)d_in[6];
    const float* gamma = (const float*)d_in[7];
    const float* beta  = (const float*)d_in[8];
    float* out = (float*)d_out;

    cudaFuncSetAttribute(fused_kernel,
                         cudaFuncAttributeMaxDynamicSharedMemorySize, GEMM_SMEM);

    w2t_kernel<<<dim3(8, 8, 24), dim3(32, 8)>>>(W2);
    pack_kernel<<<P_DIM, 256>>>();
    fused_kernel<<<GEMM_CTAS + CAT_CTAS, 512, GEMM_SMEM>>>(
        x_num, x_cat, W1, b1, b2, emb, gamma, beta, out);
}

// round 13
// speedup vs baseline: 1.1806x; 1.1806x over previous
#include <cuda_runtime.h>
#include <cuda_fp16.h>
#include <cstdint>

// ===================== Problem constants =====================
#define B_DIM 8192
#define P_DIM 24
#define Q_DIM 12
#define E_DIM 256
#define V_DIM 1000
#define LN_EPS 1e-5f

#define GEMM_CTAS 768          // 24 p * 32 mslots; each CTA: 4 tiles of 64 rows
#define CAT_CTAS 384
#define TOK_PER_CAT_CTA 256    // 98304 / 384

// fragment-packed W2: [p][ks(16)][ntp(16)][lane(32)] uint4  (3.1 MB)
__device__ uint4 g_W2Tf[P_DIM * 16 * 16 * 32];

// ===================== Prep kernel: W2 -> fragment-packed fp16 (direct) =====================
// block = (p, slice): slice = 64 e-rows of W2[p] -> ks range [slice*4, slice*4+4)
#define PREP_SMEM 65536
__global__ __launch_bounds__(256)
void prep_kernel(const float* __restrict__ W2) {
    extern __shared__ float sm[];          // [64][256] fp32 slice
    const int p  = blockIdx.x >> 2;
    const int sl = blockIdx.x & 3;
    const int e0 = sl * 64;
    const int tid = threadIdx.x;

    #pragma unroll 4
    for (int it = 0; it < 64; it++)
        sm[it * 256 + tid] = W2[((size_t)p * 256 + e0 + it) * 256 + tid];
    __syncthreads();

    const int lane = tid & 31;
    const int warp = tid >> 5;             // 0..7
    const int ksl  = warp & 3;
    const int ks   = sl * 4 + ksl;
    const int ntp0 = (warp >> 2) * 8;
    const int ne_b = lane >> 2;
    const int el0  = ksl * 16 + 2 * (lane & 3);   // local e of kh0 pair

    uint4* dstb = g_W2Tf + (size_t)p * 8192;
    #pragma unroll
    for (int j = 0; j < 8; j++) {
        const int ntp = ntp0 + j;
        const int ne = 2 * ntp * 8 + ne_b;
        const int no = ne + 8;
        uint4 v;
        __half2 h;
        h = __floats2half2_rn(sm[el0 * 256 + ne],       sm[(el0 + 1) * 256 + ne]);
        v.x = *reinterpret_cast<uint32_t*>(&h);
        h = __floats2half2_rn(sm[(el0 + 8) * 256 + ne], sm[(el0 + 9) * 256 + ne]);
        v.y = *reinterpret_cast<uint32_t*>(&h);
        h = __floats2half2_rn(sm[el0 * 256 + no],       sm[(el0 + 1) * 256 + no]);
        v.z = *reinterpret_cast<uint32_t*>(&h);
        h = __floats2half2_rn(sm[(el0 + 8) * 256 + no], sm[(el0 + 9) * 256 + no]);
        v.w = *reinterpret_cast<uint32_t*>(&h);
        dstb[(ks * 16 + ntp) * 32 + lane] = v;
    }
}

// ---- fast gelu (validated: rel_err identical to erff version) ----
__device__ __forceinline__ float fast_gelu(float t) {
    const float z  = fabsf(t) * 0.70710678118654752f;
    const float k  = __fdividef(1.0f, fmaf(0.3275911f, z, 1.0f));
    float pk = fmaf(1.061405429f, k, -1.453152027f);
    pk = fmaf(pk, k, 1.421413741f);
    pk = fmaf(pk, k, -0.284496736f);
    pk = fmaf(pk, k, 0.254829592f);
    pk = pk * k;
    const float ez   = __expf(-z * z);
    const float erfv = fmaf(-pk, ez, 1.0f);
    const float e    = (t >= 0.f) ? erfv : -erfv;
    return 0.5f * t * (1.0f + e);
}

// ===================== Fused kernel: 256 threads, 2 CTAs/SM (R11 gemm, verbatim) =====================
// SMEM byte offsets
#define SM_X    0        // 64 f
#define SM_W1   1024     // 256 f
#define SM_B1   2048
#define SM_B2   3072
#define SM_G    4096
#define SM_BE   5120
#define SM_STAT 6144     // 64 rows x 16 f = 4096 B (ends 10240)
#define SM_A    12288    // 32768 B : A frags [ks(16)][mti(4)][lane(32)] uint4
#define SM_BUF  45056    // 2 x 32768 B : B ring, chunk = [ksl(4)][ntp(16)][lane(32)] uint4
#define GEMM_SMEM 110592

__device__ __forceinline__ void mma16816(float* c, const uint32_t* a, const uint32_t* b) {
    asm volatile(
        "mma.sync.aligned.m16n8k16.row.col.f32.f16.f16.f32 "
        "{%0,%1,%2,%3}, {%4,%5,%6,%7}, {%8,%9}, {%0,%1,%2,%3};\n"
        : "+f"(c[0]), "+f"(c[1]), "+f"(c[2]), "+f"(c[3])
        : "r"(a[0]), "r"(a[1]), "r"(a[2]), "r"(a[3]), "r"(b[0]), "r"(b[1]));
}

// stage full chunk c into buf (pre-loop use)
__device__ __forceinline__ void stage_full(const uint4* __restrict__ w2f, uint4* buf,
                                           int c, int warp, int lane) {
    const int ksl = warp & 3;
    const int ntp0 = (warp >> 2) * 8;
    const uint4* src = w2f + (size_t)(c * 4 + ksl) * 512 + ntp0 * 32 + lane;
    uint4* dst = buf + (ksl * 16 + ntp0) * 32 + lane;
    #pragma unroll
    for (int i = 0; i < 8; i++)
        dst[i * 32] = src[i * 32];
}

// mma over chunk c (4 ks) from bbuf; optionally stage chunk cs into sbuf (4+4 interleaved)
template <bool STAGE>
__device__ __forceinline__ void mma_chunk(float acc[4][4][4],
                                          const uint4* __restrict__ afrag,
                                          const uint4* __restrict__ bbuf,
                                          int c, int warp, int lane,
                                          const uint4* __restrict__ w2f,
                                          uint4* sbuf, int cs) {
    const int ksl_s = warp & 3;
    const int ntp0  = (warp >> 2) * 8;
    const uint4* src = w2f + (size_t)(cs * 4 + ksl_s) * 512 + ntp0 * 32 + lane;
    uint4* dst = sbuf + (ksl_s * 16 + ntp0) * 32 + lane;

    #pragma unroll
    for (int hf = 0; hf < 2; hf++) {
        uint4 r[4];
        if (STAGE) {
            #pragma unroll
            for (int i = 0; i < 4; i++) r[i] = src[(hf * 4 + i) * 32];
        }
        #pragma unroll
        for (int kl = 0; kl < 2; kl++) {
            const int ksl = hf * 2 + kl;
            const int ks  = c * 4 + ksl;
            uint32_t a[4][4];
            #pragma unroll
            for (int mti = 0; mti < 4; mti++) {
                uint4 v = afrag[(ks * 4 + mti) * 32 + lane];
                a[mti][0] = v.x; a[mti][1] = v.y; a[mti][2] = v.z; a[mti][3] = v.w;
            }
            #pragma unroll
            for (int i = 0; i < 2; i++) {
                uint4 bv4 = bbuf[(ksl * 16 + warp * 2 + i) * 32 + lane];
                uint32_t b0[2] = {bv4.x, bv4.y};
                uint32_t b1r[2] = {bv4.z, bv4.w};
                #pragma unroll
                for (int mti = 0; mti < 4; mti++) {
                    mma16816(acc[mti][i * 2],     a[mti], b0);
                    mma16816(acc[mti][i * 2 + 1], a[mti], b1r);
                }
            }
        }
        if (STAGE) {
            #pragma unroll
            for (int i = 0; i < 4; i++) dst[(hf * 4 + i) * 32] = r[i];
        }
    }
}

__global__ __launch_bounds__(256, 2)
void fused_kernel(const float* __restrict__ x_num,
                  const int*   __restrict__ x_cat,
                  const float* __restrict__ W1,
                  const float* __restrict__ b1,
                  const float* __restrict__ b2,
                  const float* __restrict__ emb,
                  const float* __restrict__ gamma,
                  const float* __restrict__ beta,
                  float* __restrict__ out) {
    const int tid  = threadIdx.x;
    const int lane = tid & 31;
    const int warp = tid >> 5;       // 0..7

    // ================= CAT PATH: 2 independent tokens per warp-iter =================
    if (blockIdx.x >= GEMM_CTAS) {
        const int blk2 = blockIdx.x - GEMM_CTAS;
        const float4* g4  = (const float4*)gamma;
        const float4* be4 = (const float4*)beta;
        float4 g0 = g4[lane], g1 = g4[lane + 32];
        float4 e0 = be4[lane], e1 = be4[lane + 32];

        #pragma unroll 1
        for (int it = 0; it < TOK_PER_CAT_CTA / 16; it++) {
            const int tokA = blk2 * TOK_PER_CAT_CTA + it * 16 + warp * 2;
            const int tokB = tokA + 1;
            const int bA = tokA / Q_DIM, qA = tokA % Q_DIM;
            const int bB = tokB / Q_DIM, qB = tokB % Q_DIM;
            const int idxA = x_cat[(size_t)bA * Q_DIM + qA];
            const int idxB = x_cat[(size_t)bB * Q_DIM + qB];
            const float4* srcA = (const float4*)(emb + ((size_t)qA * V_DIM + idxA) * E_DIM);
            const float4* srcB = (const float4*)(emb + ((size_t)qB * V_DIM + idxB) * E_DIM);
            float4 a0 = srcA[lane], a1 = srcA[lane + 32];
            float4 c0 = srcB[lane], c1 = srcB[lane + 32];

            float sa = a0.x + a0.y + a0.z + a0.w + a1.x + a1.y + a1.z + a1.w;
            float qa = a0.x * a0.x + a0.y * a0.y + a0.z * a0.z + a0.w * a0.w
                     + a1.x * a1.x + a1.y * a1.y + a1.z * a1.z + a1.w * a1.w;
            float sb = c0.x + c0.y + c0.z + c0.w + c1.x + c1.y + c1.z + c1.w;
            float qb = c0.x * c0.x + c0.y * c0.y + c0.z * c0.z + c0.w * c0.w
                     + c1.x * c1.x + c1.y * c1.y + c1.z * c1.z + c1.w * c1.w;
            #pragma unroll
            for (int off = 16; off > 0; off >>= 1) {
                sa += __shfl_xor_sync(0xFFFFFFFFu, sa, off);
                qa += __shfl_xor_sync(0xFFFFFFFFu, qa, off);
                sb += __shfl_xor_sync(0xFFFFFFFFu, sb, off);
                qb += __shfl_xor_sync(0xFFFFFFFFu, qb, off);
            }
            const float muA = sa * (1.0f / 256.0f);
            const float rsA = rsqrtf(qa * (1.0f / 256.0f) - muA * muA + LN_EPS);
            const float muB = sb * (1.0f / 256.0f);
            const float rsB = rsqrtf(qb * (1.0f / 256.0f) - muB * muB + LN_EPS);

            float4 r0, r1;
            r0.x = (a0.x - muA) * rsA * g0.x + e0.x;
            r0.y = (a0.y - muA) * rsA * g0.y + e0.y;
            r0.z = (a0.z - muA) * rsA * g0.z + e0.z;
            r0.w = (a0.w - muA) * rsA * g0.w + e0.w;
            r1.x = (a1.x - muA) * rsA * g1.x + e1.x;
            r1.y = (a1.y - muA) * rsA * g1.y + e1.y;
            r1.z = (a1.z - muA) * rsA * g1.z + e1.z;
            r1.w = (a1.w - muA) * rsA * g1.w + e1.w;
            float4* dstA = (float4*)(out + ((size_t)bA * 36 + 24 + qA) * E_DIM);
            dstA[lane] = r0;
            dstA[lane + 32] = r1;

            r0.x = (c0.x - muB) * rsB * g0.x + e0.x;
            r0.y = (c0.y - muB) * rsB * g0.y + e0.y;
            r0.z = (c0.z - muB) * rsB * g0.z + e0.z;
            r0.w = (c0.w - muB) * rsB * g0.w + e0.w;
            r1.x = (c1.x - muB) * rsB * g1.x + e1.x;
            r1.y = (c1.y - muB) * rsB * g1.y + e1.y;
            r1.z = (c1.z - muB) * rsB * g1.z + e1.z;
            r1.w = (c1.w - muB) * rsB * g1.w + e1.w;
            float4* dstB = (float4*)(out + ((size_t)bB * 36 + 24 + qB) * E_DIM);
            dstB[lane] = r0;
            dstB[lane + 32] = r1;
        }
        return;
    }

    // ================= GEMM PATH (R11, verbatim) =================
    extern __shared__ char smem[];
    const int p     = blockIdx.x >> 5;   // 0..23
    const int mslot = blockIdx.x & 31;   // 0..31

    float* xs  = (float*)(smem + SM_X);
    float* w1s = (float*)(smem + SM_W1);
    float* b1s = (float*)(smem + SM_B1);
    float* b2s = (float*)(smem + SM_B2);
    float* gs  = (float*)(smem + SM_G);
    float* bes = (float*)(smem + SM_BE);
    float* statb = (float*)(smem + SM_STAT);         // [64][16]
    uint4* afrag = (uint4*)(smem + SM_A);
    uint4* bufs[2] = { (uint4*)(smem + SM_BUF), (uint4*)(smem + SM_BUF + 32768) };

    w1s[tid] = W1[p * 256 + tid];
    b1s[tid] = b1[p * 256 + tid];
    b2s[tid] = b2[p * 256 + tid];
    gs[tid]  = gamma[tid];
    bes[tid] = beta[tid];

    const uint4* w2f = g_W2Tf + (size_t)p * 8192;

    // pre-stage chunks 0 (buf0) and 1 (buf1)
    stage_full(w2f, bufs[0], 0, warp, lane);
    stage_full(w2f, bufs[1], 1, warp, lane);

    float2 b2v[4];
    #pragma unroll
    for (int ntl = 0; ntl < 4; ntl++)
        b2v[ntl] = *(float2*)&b2[p * 256 + warp * 32 + ntl * 8 + (lane & 3) * 2];

    // ---- Tile loop: 4 tiles of 64 rows ----
    for (int t = 0; t < 4; t++) {
        const int m0 = (mslot * 4 + t) * 64;
        const int par = t & 1;
        const int o0 = par ? 2 : 0, o1 = par ? 3 : 1;
        const int o2 = par ? 0 : 2, o3 = par ? 1 : 3;

        __syncthreads();                 // protect xs/A/stat/bufs from prev tile
        if (tid < 64) xs[tid] = x_num[(size_t)(m0 + tid) * P_DIM + p];
        __syncthreads();                 // xs ready

        // ---- Prologue: gelu -> A frags (warp covers ks = warp, warp+8) ----
        #pragma unroll
        for (int kk = 0; kk < 2; kk++) {
            const int ks = warp + kk * 8;
            const int kbase = ks * 16 + (lane & 3) * 2;
            #pragma unroll
            for (int mti = 0; mti < 4; mti++) {
                const float xm0 = xs[mti * 16 + (lane >> 2)];
                const float xm1 = xs[mti * 16 + (lane >> 2) + 8];
                uint32_t r[4];
                #pragma unroll
                for (int reg = 0; reg < 4; reg++) {
                    const float xm = (reg & 1) ? xm1 : xm0;
                    const int k = kbase + (reg & 2) * 4;
                    float h0 = fast_gelu(fmaf(xm, w1s[k],     b1s[k]));
                    float h1 = fast_gelu(fmaf(xm, w1s[k + 1], b1s[k + 1]));
                    __half2 hv = __floats2half2_rn(h0, h1);
                    r[reg] = *reinterpret_cast<uint32_t*>(&hv);
                }
                afrag[(ks * 4 + mti) * 32 + lane] = make_uint4(r[0], r[1], r[2], r[3]);
            }
        }
        __syncthreads();                 // A ready

        float acc[4][4][4];
        #pragma unroll
        for (int i = 0; i < 4; i++)
            #pragma unroll
            for (int j = 0; j < 4; j++)
                #pragma unroll
                for (int r = 0; r < 4; r++) acc[i][j][r] = 0.f;

        mma_chunk<false>(acc, afrag, bufs[o0 & 1], o0, warp, lane, w2f, nullptr, 0);
        __syncthreads();                 // all warps done reading buf[o0&1]
        mma_chunk<true >(acc, afrag, bufs[o1 & 1], o1, warp, lane, w2f, bufs[o2 & 1], o2);
        __syncthreads();                 // buf[o2&1] staged; done reading buf[o1&1]
        mma_chunk<true >(acc, afrag, bufs[o2 & 1], o2, warp, lane, w2f, bufs[o3 & 1], o3);
        __syncthreads();                 // buf[o3&1] staged
        mma_chunk<false>(acc, afrag, bufs[o3 & 1], o3, warp, lane, w2f, nullptr, 0);

        // ---- Epilogue: +b2, LayerNorm ----
        #pragma unroll
        for (int mti = 0; mti < 4; mti++)
            #pragma unroll
            for (int ntl = 0; ntl < 4; ntl++) {
                acc[mti][ntl][0] += b2v[ntl].x;
                acc[mti][ntl][1] += b2v[ntl].y;
                acc[mti][ntl][2] += b2v[ntl].x;
                acc[mti][ntl][3] += b2v[ntl].y;
            }

        #pragma unroll
        for (int mti = 0; mti < 4; mti++)
            #pragma unroll
            for (int h = 0; h < 2; h++) {
                float s = 0.f, q = 0.f;
                #pragma unroll
                for (int ntl = 0; ntl < 4; ntl++) {
                    float v0 = acc[mti][ntl][h * 2];
                    float v1 = acc[mti][ntl][h * 2 + 1];
                    s += v0 + v1;
                    q += v0 * v0 + v1 * v1;
                }
                s += __shfl_xor_sync(0xFFFFFFFFu, s, 1);
                q += __shfl_xor_sync(0xFFFFFFFFu, q, 1);
                s += __shfl_xor_sync(0xFFFFFFFFu, s, 2);
                q += __shfl_xor_sync(0xFFFFFFFFu, q, 2);
                if ((lane & 3) == 0) {
                    const int row = mti * 16 + (lane >> 2) + h * 8;
                    *(float2*)&statb[row * 16 + warp * 2] = make_float2(s, q);
                }
            }
        __syncthreads();                 // stats visible

        #pragma unroll
        for (int mti = 0; mti < 4; mti++)
            #pragma unroll
            for (int h = 0; h < 2; h++) {
                const int row = mti * 16 + (lane >> 2) + h * 8;
                float sum = 0.f, sq = 0.f;
                #pragma unroll
                for (int j = 0; j < 4; j++) {
                    float4 v = *(float4*)&statb[row * 16 + j * 4];
                    sum += v.x + v.z;
                    sq  += v.y + v.w;
                }
                const float mu   = sum * (1.0f / 256.0f);
                const float var  = sq * (1.0f / 256.0f) - mu * mu;
                const float rstd = rsqrtf(var + LN_EPS);

                float* orow = out + (((size_t)(m0 + row) * 36 + p) * 256);
                #pragma unroll
                for (int ntl = 0; ntl < 4; ntl++) {
                    const int col = warp * 32 + ntl * 8 + (lane & 3) * 2;
                    const float2 gvv = *(float2*)&gs[col];
                    const float2 bvv = *(float2*)&bes[col];
                    float2 r;
                    r.x = (acc[mti][ntl][h * 2]     - mu) * rstd * gvv.x + bvv.x;
                    r.y = (acc[mti][ntl][h * 2 + 1] - mu) * rstd * gvv.y + bvv.y;
                    *(float2*)&orow[col] = r;
                }
            }
    }
}

// ===================== Launch =====================
extern "C" void kernel_launch(void* const* d_in, const int* in_sizes, int n_in,
                              void* d_out, int out_size) {
    const float* x_num = (const float*)d_in[0];
    const int*   x_cat = (const int*)d_in[1];
    const float* W1    = (const float*)d_in[2];
    const float* b1    = (const float*)d_in[3];
    const float* W2    = (const float*)d_in[4];
    const float* b2    = (const float*)d_in[5];
    const float* emb   = (const float*)d_in[6];
    const float* gamma = (const float*)d_in[7];
    const float* beta  = (const float*)d_in[8];
    float* out = (float*)d_out;

    cudaFuncSetAttribute(prep_kernel,
                         cudaFuncAttributeMaxDynamicSharedMemorySize, PREP_SMEM);
    cudaFuncSetAttribute(fused_kernel,
                         cudaFuncAttributeMaxDynamicSharedMemorySize, GEMM_SMEM);

    prep_kernel<<<P_DIM * 4, 256, PREP_SMEM>>>(W2);
    fused_kernel<<<GEMM_CTAS + CAT_CTAS, 256, GEMM_SMEM>>>(
        x_num, x_cat, W1, b1, b2, emb, gamma, beta, out);
}